// round 1
// baseline (speedup 1.0000x reference)
#include <cuda_runtime.h>
#include <cstdint>

#define B_   32
#define NIN  4096
#define H_   32
#define G_   8
#define HD_  128
#define KSPLIT 16
#define MQKV 6144
#define MOUT 4096

typedef unsigned long long ull;

// ---------------- scratch (static device memory; no allocations) ----------------
__device__ float g_part[KSPLIT * MQKV * B_];      // split-K partials (reused by both GEMMs)
__device__ float g_qr[B_ * H_ * HD_];             // roped Q
__device__ float g_knew[B_ * G_ * HD_];           // roped new K (this step's token)
__device__ float g_vnew[B_ * G_ * HD_];           // new V
__device__ float g_att_o[B_ * G_ * 4 * 4 * HD_];  // per-split unnormalized O
__device__ float g_att_ml[B_ * G_ * 4 * 4 * 2];   // per-split (m, l)
__device__ float g_attn_out[B_ * NIN];            // attention output (X for WO gemm)

// ---------------- helpers ----------------
__device__ __forceinline__ void fma2(ull &d, ull a, ull b) {
    asm("fma.rn.f32x2 %0, %1, %2, %3;" : "=l"(d) : "l"(a), "l"(b), "l"(d));
}
__device__ __forceinline__ float pairsum(ull u) {
    return __uint_as_float((unsigned)u) + __uint_as_float((unsigned)(u >> 32));
}

// ---------------- GEMM: C[m][b] = sum_k W[m][k] * X[b][k] ----------------
// MODE 0: QKV (W rows 0..4095 = wq, 4096..5119 = wk, 5120..6143 = wv), X = x input
// MODE 1: WO,  X = g_attn_out
// grid = (M/128, KSPLIT), block = 128. Thread tile 8 rows x 4 batches, f32x2 packed.
template<int MODE>
__global__ void __launch_bounds__(128) gemm_kernel(
    const float* __restrict__ w0p, const float* __restrict__ w1p,
    const float* __restrict__ w2p, const float* __restrict__ Xp, int M)
{
    __shared__ __align__(16) float xs[32 * 68];   // X panel [32 batches][64 k], pad 68
    const int tid  = threadIdx.x;
    const int tm   = tid >> 3;       // 0..15 row group
    const int tn   = tid & 7;        // 0..7  batch group
    const int b0   = tn << 2;        // 4 batches per thread
    const int mblk = blockIdx.x;
    const int ksl  = blockIdx.y;
    const int mrow0 = mblk << 7;

    const float* X = (MODE == 0) ? Xp : g_attn_out;
    const float* Wb;
    if (MODE == 0) {
        if (mblk < 32)      Wb = w0p + (size_t)mrow0 * NIN;
        else if (mblk < 40) Wb = w1p + (size_t)(mrow0 - 4096) * NIN;
        else                Wb = w2p + (size_t)(mrow0 - 5120) * NIN;
    } else {
        Wb = w0p + (size_t)mrow0 * NIN;
    }
    const int k0 = ksl << 8;   // 256 k per split

    ull acc[8][4];
    #pragma unroll
    for (int r = 0; r < 8; r++)
        #pragma unroll
        for (int j = 0; j < 4; j++) acc[r][j] = 0ull;

    for (int ch = 0; ch < 4; ch++) {
        const int kb = k0 + (ch << 6);
        // load X panel (coalesced float4)
        #pragma unroll
        for (int i = 0; i < 4; i++) {
            int f  = tid + (i << 7);
            int bb = f >> 4, k4 = f & 15;
            float4 v = *(const float4*)(X + (size_t)bb * NIN + kb + (k4 << 2));
            *(float4*)&xs[bb * 68 + (k4 << 2)] = v;
        }
        __syncthreads();
        #pragma unroll
        for (int kk = 0; kk < 64; kk += 4) {
            ull wa[8], wbv[8];
            #pragma unroll
            for (int r = 0; r < 8; r++) {
                ulonglong2 wd = *(const ulonglong2*)(Wb + (size_t)(tm + (r << 4)) * NIN + kb + kk);
                wa[r] = wd.x; wbv[r] = wd.y;
            }
            ull xa[4], xb[4];
            #pragma unroll
            for (int j = 0; j < 4; j++) {
                ulonglong2 xd = *(const ulonglong2*)&xs[(b0 + j) * 68 + kk];
                xa[j] = xd.x; xb[j] = xd.y;
            }
            #pragma unroll
            for (int r = 0; r < 8; r++)
                #pragma unroll
                for (int j = 0; j < 4; j++) {
                    fma2(acc[r][j], wa[r],  xa[j]);
                    fma2(acc[r][j], wbv[r], xb[j]);
                }
        }
        __syncthreads();
    }
    // store partial: part[ks][m][b], coalesced float4 per row
    float* outp = g_part + (size_t)ksl * M * B_;
    #pragma unroll
    for (int r = 0; r < 8; r++) {
        int m = mrow0 + tm + (r << 4);
        float4 o;
        o.x = pairsum(acc[r][0]); o.y = pairsum(acc[r][1]);
        o.z = pairsum(acc[r][2]); o.w = pairsum(acc[r][3]);
        *(float4*)(outp + (size_t)m * B_ + b0) = o;
    }
}

// ---------------- split-K reduce + RoPE ----------------
// grid = (48 m-chunks of 128, 4 batch-quarters), block = 256
// chunk c: c<32 -> q head c (rope), 32..39 -> k group (rope), 40..47 -> v group (copy)
__global__ void __launch_bounds__(256) reduce_rope_kernel(
    const float* __restrict__ cosp, const float* __restrict__ sinp)
{
    __shared__ float sm[128 * 9];
    const int c  = blockIdx.x;
    const int b0 = blockIdx.y << 3;
    const int m0 = c << 7;
    for (int idx = threadIdx.x; idx < 1024; idx += 256) {
        int ml = idx >> 3, bl = idx & 7;
        const float* p = g_part + (size_t)(m0 + ml) * B_ + b0 + bl;
        float s = 0.f;
        #pragma unroll
        for (int ks = 0; ks < KSPLIT; ks++) s += p[(size_t)ks * MQKV * B_];
        sm[ml * 9 + bl] = s;
    }
    __syncthreads();
    for (int idx = threadIdx.x; idx < 1024; idx += 256) {
        int bl = idx >> 7, d = idx & 127;
        int b  = b0 + bl;
        float t = sm[d * 9 + bl];
        float outv;
        if (c < 40) {
            float rot = (d < 64) ? -sm[(d + 64) * 9 + bl] : sm[(d - 64) * 9 + bl];
            outv = t * cosp[b * HD_ + d] + rot * sinp[b * HD_ + d];
        } else outv = t;
        if (c < 32)      g_qr[((size_t)b * H_ + c) * HD_ + d]          = outv;
        else if (c < 40) g_knew[((size_t)b * G_ + (c - 32)) * HD_ + d] = outv;
        else             g_vnew[((size_t)b * G_ + (c - 40)) * HD_ + d] = outv;
    }
}

// ---------------- paged attention, flash-decoding ----------------
// grid = (4 splits, G, B), block = 256 (8 warps). Each warp: online softmax over
// its token stripe for the 4 heads of this group; block-level merge; per-split partial.
__global__ void __launch_bounds__(256) attn_kernel(
    const float* __restrict__ kc, const float* __restrict__ vc,
    const int* __restrict__ bt, const int* __restrict__ ctxl)
{
    __shared__ __align__(16) float qs[512];
    __shared__ __align__(16) float wo_s[8][512];
    __shared__ float wm[8][4];
    __shared__ float wl[8][4];
    const int sx = blockIdx.x, g = blockIdx.y, b = blockIdx.z;
    const int tid = threadIdx.x, w = tid >> 5, lane = tid & 31;

    for (int i = tid; i < 512; i += 256)
        qs[i] = g_qr[((size_t)b * H_ + g * 4) * HD_ + i];
    __syncthreads();

    const int ctx   = ctxl[b];
    const int t0    = sx << 9;
    const int t1    = min(t0 + 512, ctx);
    const int lastt = ctx - 1;
    const float scale = 0.08838834764831843f;   // 1/sqrt(128)

    const float4 q0 = *(const float4*)&qs[0 * 128 + (lane << 2)];
    const float4 q1 = *(const float4*)&qs[1 * 128 + (lane << 2)];
    const float4 q2 = *(const float4*)&qs[2 * 128 + (lane << 2)];
    const float4 q3 = *(const float4*)&qs[3 * 128 + (lane << 2)];

    float m0 = -1e30f, m1 = -1e30f, m2 = -1e30f, m3 = -1e30f;
    float l0 = 0.f, l1 = 0.f, l2 = 0.f, l3 = 0.f;
    float4 a0 = {0,0,0,0}, a1 = {0,0,0,0}, a2 = {0,0,0,0}, a3 = {0,0,0,0};

    for (int t = t0 + w; t < t1; t += 8) {
        float4 k4, v4;
        if (t == lastt) {
            k4 = *(const float4*)(g_knew + ((size_t)b * G_ + g) * HD_ + (lane << 2));
            v4 = *(const float4*)(g_vnew + ((size_t)b * G_ + g) * HD_ + (lane << 2));
        } else {
            int blk = __ldg(&bt[b * 128 + (t >> 4)]);
            size_t row = (((size_t)blk * 16 + (t & 15)) * G_ + g) * HD_ + (lane << 2);
            k4 = *(const float4*)(kc + row);
            v4 = *(const float4*)(vc + row);
        }
        float s0 = fmaf(k4.x, q0.x, fmaf(k4.y, q0.y, fmaf(k4.z, q0.z, k4.w * q0.w)));
        float s1 = fmaf(k4.x, q1.x, fmaf(k4.y, q1.y, fmaf(k4.z, q1.z, k4.w * q1.w)));
        float s2 = fmaf(k4.x, q2.x, fmaf(k4.y, q2.y, fmaf(k4.z, q2.z, k4.w * q2.w)));
        float s3 = fmaf(k4.x, q3.x, fmaf(k4.y, q3.y, fmaf(k4.z, q3.z, k4.w * q3.w)));
        #pragma unroll
        for (int off = 16; off; off >>= 1) {
            s0 += __shfl_xor_sync(0xffffffffu, s0, off);
            s1 += __shfl_xor_sync(0xffffffffu, s1, off);
            s2 += __shfl_xor_sync(0xffffffffu, s2, off);
            s3 += __shfl_xor_sync(0xffffffffu, s3, off);
        }
        s0 *= scale; s1 *= scale; s2 *= scale; s3 *= scale;
        { float nm = fmaxf(m0, s0); float al = __expf(m0 - nm); float p = __expf(s0 - nm);
          l0 = l0 * al + p; m0 = nm;
          a0.x = fmaf(p, v4.x, a0.x * al); a0.y = fmaf(p, v4.y, a0.y * al);
          a0.z = fmaf(p, v4.z, a0.z * al); a0.w = fmaf(p, v4.w, a0.w * al); }
        { float nm = fmaxf(m1, s1); float al = __expf(m1 - nm); float p = __expf(s1 - nm);
          l1 = l1 * al + p; m1 = nm;
          a1.x = fmaf(p, v4.x, a1.x * al); a1.y = fmaf(p, v4.y, a1.y * al);
          a1.z = fmaf(p, v4.z, a1.z * al); a1.w = fmaf(p, v4.w, a1.w * al); }
        { float nm = fmaxf(m2, s2); float al = __expf(m2 - nm); float p = __expf(s2 - nm);
          l2 = l2 * al + p; m2 = nm;
          a2.x = fmaf(p, v4.x, a2.x * al); a2.y = fmaf(p, v4.y, a2.y * al);
          a2.z = fmaf(p, v4.z, a2.z * al); a2.w = fmaf(p, v4.w, a2.w * al); }
        { float nm = fmaxf(m3, s3); float al = __expf(m3 - nm); float p = __expf(s3 - nm);
          l3 = l3 * al + p; m3 = nm;
          a3.x = fmaf(p, v4.x, a3.x * al); a3.y = fmaf(p, v4.y, a3.y * al);
          a3.z = fmaf(p, v4.z, a3.z * al); a3.w = fmaf(p, v4.w, a3.w * al); }
    }

    *(float4*)&wo_s[w][0 * 128 + (lane << 2)] = a0;
    *(float4*)&wo_s[w][1 * 128 + (lane << 2)] = a1;
    *(float4*)&wo_s[w][2 * 128 + (lane << 2)] = a2;
    *(float4*)&wo_s[w][3 * 128 + (lane << 2)] = a3;
    if (lane == 0) {
        wm[w][0] = m0; wm[w][1] = m1; wm[w][2] = m2; wm[w][3] = m3;
        wl[w][0] = l0; wl[w][1] = l1; wl[w][2] = l2; wl[w][3] = l3;
    }
    __syncthreads();

    const int base = (b * G_ + g) * 4 + sx;
    for (int i = tid; i < 512; i += 256) {
        int r = i >> 7, d = i & 127;
        float gm = -1e30f;
        #pragma unroll
        for (int ww = 0; ww < 8; ww++) gm = fmaxf(gm, wm[ww][r]);
        float L = 0.f, o = 0.f;
        #pragma unroll
        for (int ww = 0; ww < 8; ww++) {
            float e = __expf(wm[ww][r] - gm);   // empty warps: l=0, acc=0 -> harmless
            L += e * wl[ww][r];
            o += e * wo_s[ww][r * 128 + d];
        }
        g_att_o[(size_t)base * 512 + r * 128 + d] = o;
        if (d == 0) {
            g_att_ml[base * 8 + r * 2 + 0] = gm;
            g_att_ml[base * 8 + r * 2 + 1] = L;
        }
    }
}

// ---------------- combine splits -> normalized attention output ----------------
__global__ void __launch_bounds__(128) attn_reduce_kernel()
{
    const int h = blockIdx.x, b = blockIdx.y, d = threadIdx.x;
    const int g = h >> 2, r = h & 3;
    const int base0 = (b * G_ + g) * 4;
    float gm = -1e30f;
    #pragma unroll
    for (int sx = 0; sx < 4; sx++) gm = fmaxf(gm, g_att_ml[(base0 + sx) * 8 + r * 2]);
    float L = 0.f, o = 0.f;
    #pragma unroll
    for (int sx = 0; sx < 4; sx++) {
        float mm = g_att_ml[(base0 + sx) * 8 + r * 2];
        float ll = g_att_ml[(base0 + sx) * 8 + r * 2 + 1];
        float e  = __expf(mm - gm);
        L += e * ll;
        o += e * g_att_o[(size_t)(base0 + sx) * 512 + r * 128 + d];
    }
    g_attn_out[(size_t)b * NIN + h * HD_ + d] = o / L;
}

// ---------------- split-K reduce of WO gemm -> final output ----------------
__global__ void __launch_bounds__(256) reduce_out_kernel(float* __restrict__ out)
{
    __shared__ float sm[128 * 9];
    const int c  = blockIdx.x;
    const int b0 = blockIdx.y << 3;
    const int m0 = c << 7;
    for (int idx = threadIdx.x; idx < 1024; idx += 256) {
        int ml = idx >> 3, bl = idx & 7;
        const float* p = g_part + (size_t)(m0 + ml) * B_ + b0 + bl;
        float s = 0.f;
        #pragma unroll
        for (int ks = 0; ks < KSPLIT; ks++) s += p[(size_t)ks * MOUT * B_];
        sm[ml * 9 + bl] = s;
    }
    __syncthreads();
    for (int idx = threadIdx.x; idx < 1024; idx += 256) {
        int bl = idx >> 7, ml = idx & 127;
        out[(size_t)(b0 + bl) * NIN + m0 + ml] = sm[ml * 9 + bl];
    }
}

// ---------------- launch ----------------
extern "C" void kernel_launch(void* const* d_in, const int* in_sizes, int n_in,
                              void* d_out, int out_size)
{
    const float* x  = (const float*)d_in[0];
    const float* wq = (const float*)d_in[1];
    const float* wk = (const float*)d_in[2];
    const float* wv = (const float*)d_in[3];
    const float* wo = (const float*)d_in[4];
    const float* kc = (const float*)d_in[5];
    const float* vc = (const float*)d_in[6];
    const float* cs = (const float*)d_in[7];
    const float* sn = (const float*)d_in[8];
    // d_in[9] = slot_mapping (unused: slot == (b, ctx-1) by construction)
    const int* ctx = (const int*)d_in[10];
    const int* bt  = (const int*)d_in[11];
    float* out = (float*)d_out;

    gemm_kernel<0><<<dim3(48, KSPLIT), 128>>>(wq, wk, wv, x, MQKV);
    reduce_rope_kernel<<<dim3(48, 4), 256>>>(cs, sn);
    attn_kernel<<<dim3(4, G_, B_), 256>>>(kc, vc, bt, ctx);
    attn_reduce_kernel<<<dim3(H_, B_), 128>>>();
    gemm_kernel<1><<<dim3(32, KSPLIT), 128>>>(wo, wo, wo, nullptr, MOUT);
    reduce_out_kernel<<<dim3(32, 4), 256>>>(out);
}

// round 4
// speedup vs baseline: 1.1321x; 1.1321x over previous
#include <cuda_runtime.h>
#include <cstdint>

#define B_   32
#define NIN  4096
#define H_   32
#define G_   8
#define HD_  128
#define KS   4
#define MQKV 6144
#define MOUT 4096

typedef unsigned int u32;
typedef unsigned long long ull;

// ---------------- scratch (static device memory) ----------------
__device__ float g_part[KS * MQKV * B_];          // split-K partials (shared by both GEMMs)
__device__ float g_qr[B_ * H_ * HD_];             // roped Q
__device__ float g_knew[B_ * G_ * HD_];           // roped new K
__device__ float g_vnew[B_ * G_ * HD_];           // new V
__device__ float g_att_o[B_ * G_ * 4 * 4 * HD_];  // per-split unnormalized O
__device__ float g_att_ml[B_ * G_ * 4 * 4 * 2];   // per-split (m, l)
__device__ u32   g_xh[B_ * NIN / 2];              // x packed bf16x2 hi
__device__ u32   g_xl[B_ * NIN / 2];              // x packed bf16x2 lo
__device__ u32   g_yh[B_ * NIN / 2];              // attn-out packed hi
__device__ u32   g_yl[B_ * NIN / 2];              // attn-out packed lo

// ---------------- helpers ----------------
// split pair (x0,x1) into bf16x2 hi + bf16x2 lo (error-compensated split)
__device__ __forceinline__ void split2(float x0, float x1, u32 &hi, u32 &lo) {
    u32 h;
    asm("cvt.rn.bf16x2.f32 %0, %1, %2;" : "=r"(h) : "f"(x1), "f"(x0));
    float h0 = __uint_as_float(h << 16);
    float h1 = __uint_as_float(h & 0xffff0000u);
    float l0 = x0 - h0, l1 = x1 - h1;
    u32 l;
    asm("cvt.rn.bf16x2.f32 %0, %1, %2;" : "=r"(l) : "f"(l1), "f"(l0));
    hi = h; lo = l;
}

__device__ __forceinline__ void mma16816(float* c, u32 a0, u32 a1, u32 a2, u32 a3,
                                         u32 b0, u32 b1) {
    asm("mma.sync.aligned.m16n8k16.row.col.f32.bf16.bf16.f32 "
        "{%0,%1,%2,%3}, {%4,%5,%6,%7}, {%8,%9}, {%0,%1,%2,%3};"
        : "+f"(c[0]), "+f"(c[1]), "+f"(c[2]), "+f"(c[3])
        : "r"(a0), "r"(a1), "r"(a2), "r"(a3), "r"(b0), "r"(b1));
}

// ---------------- pack x -> bf16x2 hi/lo ----------------
__global__ void __launch_bounds__(256) xpack_kernel(const float* __restrict__ x)
{
    for (int idx = blockIdx.x * 256 + threadIdx.x; idx < B_ * NIN / 2;
         idx += gridDim.x * 256) {
        float2 v = *(const float2*)(x + (size_t)idx * 2);
        u32 h, l;
        split2(v.x, v.y, h, l);
        g_xh[idx] = h; g_xl[idx] = l;
    }
}

// ---------------- tensor-core GEMM: part[ks][m][b] = sum_k W[m][k] X[b][k] ----------------
// MODE 0: QKV (wq rows 0..4095 -> blocks 0..63, wk -> 64..79, wv -> 80..95), B = g_x{h,l}
// MODE 1: WO (blocks 0..63), B = g_y{h,l}
// grid (M/64, KS), block 128 (4 warps, each warp owns 16 rows x all 32 batches).
// k-mapping permutation: hardware k slots {2t,2t+1,2t+8,2t+9} remapped to {4t..4t+3},
// applied identically to A and B fragments, so the result is exact.
template<int MODE>
__global__ void __launch_bounds__(128) gemm_mma_kernel(
    const float* __restrict__ w0p, const float* __restrict__ w1p,
    const float* __restrict__ w2p, int M)
{
    const int tid  = threadIdx.x;
    const int w    = tid >> 5;
    const int lane = tid & 31;
    const int g    = lane >> 2;
    const int tg   = lane & 3;
    const int mblk = blockIdx.x;
    const int ksl  = blockIdx.y;
    const int mrow0 = mblk << 6;           // 64 rows per block

    const u32* __restrict__ xh = (MODE == 0) ? g_xh : g_yh;
    const u32* __restrict__ xl = (MODE == 0) ? g_xl : g_yl;

    const float* Wb;
    if (MODE == 0) {
        if (mblk < 64)      Wb = w0p + (size_t)mrow0 * NIN;
        else if (mblk < 80) Wb = w1p + (size_t)(mrow0 - 4096) * NIN;
        else                Wb = w2p + (size_t)(mrow0 - 5120) * NIN;
    } else {
        Wb = w0p + (size_t)mrow0 * NIN;
    }
    const int rloc = (w << 4) + g;                         // warp-local row (0..63)
    const float* pa = Wb + (size_t)rloc * NIN + (tg << 2); // row g
    const float* pb = pa + 8 * NIN;                        // row g+8

    // B pointers: 4 n-tiles, this thread holds column n = 8j + g
    const u32* pbh[4]; const u32* pbl[4];
    #pragma unroll
    for (int j = 0; j < 4; j++) {
        int n = (j << 3) + g;
        pbh[j] = xh + (size_t)n * (NIN / 2) + (tg << 1);
        pbl[j] = xl + (size_t)n * (NIN / 2) + (tg << 1);
    }

    float c[4][4];
    #pragma unroll
    for (int j = 0; j < 4; j++)
        #pragma unroll
        for (int i = 0; i < 4; i++) c[j][i] = 0.f;

    const int k0 = ksl << 10;    // 1024 k per split
    #pragma unroll 2
    for (int s = 0; s < 64; s++) {
        const int k = k0 + (s << 4);
        // A: two float4 loads cover the full 16-k fragment (permuted mapping)
        float4 wa = *(const float4*)(pa + k);
        float4 wb = *(const float4*)(pb + k);
        u32 a0h, a0l, a2h, a2l, a1h, a1l, a3h, a3l;
        split2(wa.x, wa.y, a0h, a0l);
        split2(wa.z, wa.w, a2h, a2l);
        split2(wb.x, wb.y, a1h, a1l);
        split2(wb.z, wb.w, a3h, a3l);

        const int kh = (k >> 1);
        #pragma unroll
        for (int j = 0; j < 4; j++) {
            uint2 bh = *(const uint2*)(pbh[j] + kh);
            uint2 bl = *(const uint2*)(pbl[j] + kh);
            mma16816(c[j], a0h, a1h, a2h, a3h, bh.x, bh.y);   // hi*hi
            mma16816(c[j], a0h, a1h, a2h, a3h, bl.x, bl.y);   // hi*lo
            mma16816(c[j], a0l, a1l, a2l, a3l, bh.x, bh.y);   // lo*hi
        }
    }

    // store partials: part[ksl][m][b]
    float* op = g_part + (size_t)ksl * M * B_ + (size_t)(mrow0 + rloc) * B_;
    #pragma unroll
    for (int j = 0; j < 4; j++) {
        int n = (j << 3) + (tg << 1);
        *(float2*)(op + n)           = make_float2(c[j][0], c[j][1]);
        *(float2*)(op + 8 * B_ + n)  = make_float2(c[j][2], c[j][3]);   // row +8
    }
}

// ---------------- split-K reduce + RoPE ----------------
// grid (48, 4), block 256. chunk c: c<32 -> q head (rope), 32..39 -> k (rope), 40..47 -> v
__global__ void __launch_bounds__(256) reduce_rope_kernel(
    const float* __restrict__ cosp, const float* __restrict__ sinp)
{
    __shared__ float sm[128 * 9];
    const int c  = blockIdx.x;
    const int b0 = blockIdx.y << 3;
    const int m0 = c << 7;
    for (int idx = threadIdx.x; idx < 1024; idx += 256) {
        int ml = idx >> 3, bl = idx & 7;
        const float* p = g_part + (size_t)(m0 + ml) * B_ + b0 + bl;
        float s = 0.f;
        #pragma unroll
        for (int ks = 0; ks < KS; ks++) s += p[(size_t)ks * MQKV * B_];
        sm[ml * 9 + bl] = s;
    }
    __syncthreads();
    for (int idx = threadIdx.x; idx < 1024; idx += 256) {
        int bl = idx >> 7, d = idx & 127;
        int b  = b0 + bl;
        float t = sm[d * 9 + bl];
        float outv;
        if (c < 40) {
            float rot = (d < 64) ? -sm[(d + 64) * 9 + bl] : sm[(d - 64) * 9 + bl];
            outv = t * cosp[b * HD_ + d] + rot * sinp[b * HD_ + d];
        } else outv = t;
        if (c < 32)      g_qr[((size_t)b * H_ + c) * HD_ + d]          = outv;
        else if (c < 40) g_knew[((size_t)b * G_ + (c - 32)) * HD_ + d] = outv;
        else             g_vnew[((size_t)b * G_ + (c - 40)) * HD_ + d] = outv;
    }
}

// ---------------- paged attention, flash-decoding ----------------
__global__ void __launch_bounds__(256) attn_kernel(
    const float* __restrict__ kc, const float* __restrict__ vc,
    const int* __restrict__ bt, const int* __restrict__ ctxl)
{
    __shared__ __align__(16) float qs[512];
    __shared__ __align__(16) float wo_s[8][512];
    __shared__ float wm[8][4];
    __shared__ float wl[8][4];
    const int sx = blockIdx.x, g = blockIdx.y, b = blockIdx.z;
    const int tid = threadIdx.x, w = tid >> 5, lane = tid & 31;

    for (int i = tid; i < 512; i += 256)
        qs[i] = g_qr[((size_t)b * H_ + g * 4) * HD_ + i];
    __syncthreads();

    const int ctx   = ctxl[b];
    const int t0    = sx << 9;
    const int t1    = min(t0 + 512, ctx);
    const int lastt = ctx - 1;
    const float scale = 0.08838834764831843f;   // 1/sqrt(128)

    const float4 q0 = *(const float4*)&qs[0 * 128 + (lane << 2)];
    const float4 q1 = *(const float4*)&qs[1 * 128 + (lane << 2)];
    const float4 q2 = *(const float4*)&qs[2 * 128 + (lane << 2)];
    const float4 q3 = *(const float4*)&qs[3 * 128 + (lane << 2)];

    float m0 = -1e30f, m1 = -1e30f, m2 = -1e30f, m3 = -1e30f;
    float l0 = 0.f, l1 = 0.f, l2 = 0.f, l3 = 0.f;
    float4 a0 = {0,0,0,0}, a1 = {0,0,0,0}, a2 = {0,0,0,0}, a3 = {0,0,0,0};

    for (int t = t0 + w; t < t1; t += 8) {
        float4 k4, v4;
        if (t == lastt) {
            k4 = *(const float4*)(g_knew + ((size_t)b * G_ + g) * HD_ + (lane << 2));
            v4 = *(const float4*)(g_vnew + ((size_t)b * G_ + g) * HD_ + (lane << 2));
        } else {
            int blk = __ldg(&bt[b * 128 + (t >> 4)]);
            size_t row = (((size_t)blk * 16 + (t & 15)) * G_ + g) * HD_ + (lane << 2);
            k4 = *(const float4*)(kc + row);
            v4 = *(const float4*)(vc + row);
        }
        float s0 = fmaf(k4.x, q0.x, fmaf(k4.y, q0.y, fmaf(k4.z, q0.z, k4.w * q0.w)));
        float s1 = fmaf(k4.x, q1.x, fmaf(k4.y, q1.y, fmaf(k4.z, q1.z, k4.w * q1.w)));
        float s2 = fmaf(k4.x, q2.x, fmaf(k4.y, q2.y, fmaf(k4.z, q2.z, k4.w * q2.w)));
        float s3 = fmaf(k4.x, q3.x, fmaf(k4.y, q3.y, fmaf(k4.z, q3.z, k4.w * q3.w)));
        #pragma unroll
        for (int off = 16; off; off >>= 1) {
            s0 += __shfl_xor_sync(0xffffffffu, s0, off);
            s1 += __shfl_xor_sync(0xffffffffu, s1, off);
            s2 += __shfl_xor_sync(0xffffffffu, s2, off);
            s3 += __shfl_xor_sync(0xffffffffu, s3, off);
        }
        s0 *= scale; s1 *= scale; s2 *= scale; s3 *= scale;
        // branchy online softmax: rescale only on new max (warp-uniform branch)
        float p0, p1, p2, p3;
        if (s0 > m0) { float al = __expf(m0 - s0); m0 = s0; l0 *= al;
                       a0.x *= al; a0.y *= al; a0.z *= al; a0.w *= al; p0 = 1.f; }
        else p0 = __expf(s0 - m0);
        if (s1 > m1) { float al = __expf(m1 - s1); m1 = s1; l1 *= al;
                       a1.x *= al; a1.y *= al; a1.z *= al; a1.w *= al; p1 = 1.f; }
        else p1 = __expf(s1 - m1);
        if (s2 > m2) { float al = __expf(m2 - s2); m2 = s2; l2 *= al;
                       a2.x *= al; a2.y *= al; a2.z *= al; a2.w *= al; p2 = 1.f; }
        else p2 = __expf(s2 - m2);
        if (s3 > m3) { float al = __expf(m3 - s3); m3 = s3; l3 *= al;
                       a3.x *= al; a3.y *= al; a3.z *= al; a3.w *= al; p3 = 1.f; }
        else p3 = __expf(s3 - m3);
        l0 += p0; l1 += p1; l2 += p2; l3 += p3;
        a0.x = fmaf(p0, v4.x, a0.x); a0.y = fmaf(p0, v4.y, a0.y);
        a0.z = fmaf(p0, v4.z, a0.z); a0.w = fmaf(p0, v4.w, a0.w);
        a1.x = fmaf(p1, v4.x, a1.x); a1.y = fmaf(p1, v4.y, a1.y);
        a1.z = fmaf(p1, v4.z, a1.z); a1.w = fmaf(p1, v4.w, a1.w);
        a2.x = fmaf(p2, v4.x, a2.x); a2.y = fmaf(p2, v4.y, a2.y);
        a2.z = fmaf(p2, v4.z, a2.z); a2.w = fmaf(p2, v4.w, a2.w);
        a3.x = fmaf(p3, v4.x, a3.x); a3.y = fmaf(p3, v4.y, a3.y);
        a3.z = fmaf(p3, v4.z, a3.z); a3.w = fmaf(p3, v4.w, a3.w);
    }

    *(float4*)&wo_s[w][0 * 128 + (lane << 2)] = a0;
    *(float4*)&wo_s[w][1 * 128 + (lane << 2)] = a1;
    *(float4*)&wo_s[w][2 * 128 + (lane << 2)] = a2;
    *(float4*)&wo_s[w][3 * 128 + (lane << 2)] = a3;
    if (lane == 0) {
        wm[w][0] = m0; wm[w][1] = m1; wm[w][2] = m2; wm[w][3] = m3;
        wl[w][0] = l0; wl[w][1] = l1; wl[w][2] = l2; wl[w][3] = l3;
    }
    __syncthreads();

    const int base = (b * G_ + g) * 4 + sx;
    for (int i = tid; i < 512; i += 256) {
        int r = i >> 7, d = i & 127;
        float gm = -1e30f;
        #pragma unroll
        for (int ww = 0; ww < 8; ww++) gm = fmaxf(gm, wm[ww][r]);
        float L = 0.f, o = 0.f;
        #pragma unroll
        for (int ww = 0; ww < 8; ww++) {
            float e = __expf(wm[ww][r] - gm);   // empty warps: l=0, acc=0 -> harmless
            L += e * wl[ww][r];
            o += e * wo_s[ww][r * 128 + d];
        }
        g_att_o[(size_t)base * 512 + r * 128 + d] = o;
        if (d == 0) {
            g_att_ml[base * 8 + r * 2 + 0] = gm;
            g_att_ml[base * 8 + r * 2 + 1] = L;
        }
    }
}

// ---------------- combine splits -> packed bf16 hi/lo Y for WO GEMM ----------------
// grid (H_, B_), block 64: thread t handles d = 2t, 2t+1
__global__ void __launch_bounds__(64) attn_reduce_kernel()
{
    const int h = blockIdx.x, b = blockIdx.y, t = threadIdx.x;
    const int g = h >> 2, r = h & 3;
    const int d0 = t << 1;
    const int base0 = (b * G_ + g) * 4;
    float gm = -1e30f;
    #pragma unroll
    for (int sx = 0; sx < 4; sx++) gm = fmaxf(gm, g_att_ml[(base0 + sx) * 8 + r * 2]);
    float L = 0.f, o0 = 0.f, o1 = 0.f;
    #pragma unroll
    for (int sx = 0; sx < 4; sx++) {
        float mm = g_att_ml[(base0 + sx) * 8 + r * 2];
        float ll = g_att_ml[(base0 + sx) * 8 + r * 2 + 1];
        float e  = __expf(mm - gm);
        L += e * ll;
        float2 ov = *(const float2*)(g_att_o + (size_t)(base0 + sx) * 512 + r * 128 + d0);
        o0 = fmaf(e, ov.x, o0); o1 = fmaf(e, ov.y, o1);
    }
    float inv = 1.f / L;
    o0 *= inv; o1 *= inv;
    u32 hi, lo;
    split2(o0, o1, hi, lo);
    int idx = b * (NIN / 2) + h * (HD_ / 2) + t;
    g_yh[idx] = hi; g_yl[idx] = lo;
}

// ---------------- split-K reduce of WO gemm -> final output ----------------
__global__ void __launch_bounds__(256) reduce_out_kernel(float* __restrict__ out)
{
    __shared__ float sm[128 * 9];
    const int c  = blockIdx.x;
    const int b0 = blockIdx.y << 3;
    const int m0 = c << 7;
    for (int idx = threadIdx.x; idx < 1024; idx += 256) {
        int ml = idx >> 3, bl = idx & 7;
        const float* p = g_part + (size_t)(m0 + ml) * B_ + b0 + bl;
        float s = 0.f;
        #pragma unroll
        for (int ks = 0; ks < KS; ks++) s += p[(size_t)ks * MOUT * B_];
        sm[ml * 9 + bl] = s;
    }
    __syncthreads();
    for (int idx = threadIdx.x; idx < 1024; idx += 256) {
        int bl = idx >> 7, ml = idx & 127;
        out[(size_t)(b0 + bl) * NIN + m0 + ml] = sm[ml * 9 + bl];
    }
}

// ---------------- launch ----------------
extern "C" void kernel_launch(void* const* d_in, const int* in_sizes, int n_in,
                              void* d_out, int out_size)
{
    const float* x  = (const float*)d_in[0];
    const float* wq = (const float*)d_in[1];
    const float* wk = (const float*)d_in[2];
    const float* wv = (const float*)d_in[3];
    const float* wo = (const float*)d_in[4];
    const float* kc = (const float*)d_in[5];
    const float* vc = (const float*)d_in[6];
    const float* cs = (const float*)d_in[7];
    const float* sn = (const float*)d_in[8];
    // d_in[9] = slot_mapping (slot == (b, ctx-1) by construction)
    const int* ctx = (const int*)d_in[10];
    const int* bt  = (const int*)d_in[11];
    float* out = (float*)d_out;

    xpack_kernel<<<256, 256>>>(x);
    gemm_mma_kernel<0><<<dim3(96, KS), 128>>>(wq, wk, wv, MQKV);
    reduce_rope_kernel<<<dim3(48, 4), 256>>>(cs, sn);
    attn_kernel<<<dim3(4, G_, B_), 256>>>(kc, vc, bt, ctx);
    attn_reduce_kernel<<<dim3(H_, B_), 64>>>();
    gemm_mma_kernel<1><<<dim3(64, KS), 128>>>(wo, wo, wo, MOUT);
    reduce_out_kernel<<<dim3(32, 4), 256>>>(out);
}